// round 7
// baseline (speedup 1.0000x reference)
#include <cuda_runtime.h>

// Problem constants (fixed by the reference):
//   B=16384, N_OBJ=16, N_ATTR=4, N_PARAM=2, DIM_IN=256, D_ATTR=8
//   out[b,o,a,p,k]  -> per object o: GEMM [B,256] x [256,64]
#define THREADS   256
#define BT        256          // batch rows per block
#define KC        32           // k-chunk staged in smem
#define DIM       256          // DIM_IN
#define COLS      64           // N_ATTR*N_PARAM*D_ATTR
#define XS_STRIDE (BT + 1)     // pad -> conflict-free transpose store + read

__device__ __forceinline__ void fma2(unsigned long long& d,
                                     unsigned long long a,
                                     unsigned long long b) {
    // packed 2-wide fp32 FMA (FFMA2) — 2x the FFMA issue-rate-limited throughput
    asm("fma.rn.f32x2 %0, %1, %2, %0;" : "+l"(d) : "l"(a), "l"(b));
}

__device__ __forceinline__ unsigned long long bcast2(float v) {
    unsigned long long r;
    asm("mov.b64 %0, {%1, %1};" : "=l"(r) : "f"(v));
    return r;
}

__global__ __launch_bounds__(THREADS, 2)
void obj_decoder_kernel(const float* __restrict__ x,      // [B,16,256]
                        const float* __restrict__ W,      // [16,4,2,256,8]
                        const float* __restrict__ bias,   // [16,4,2,8]
                        float* __restrict__ out) {        // [B,16,4,2,8]
    extern __shared__ float sm[];
    float* Ws = sm;                        // [DIM][COLS]  = 64 KB, Ws[d][c]
    float* xs = sm + DIM * COLS;           // [KC][XS_STRIDE] ~ 32.9 KB, xs[k][row]
    float* bs = xs + KC * XS_STRIDE;       // [COLS]

    const int o    = blockIdx.y;
    const int row0 = blockIdx.x * BT;

    // ---- Load W[o] into smem as Ws[d][c], c = (a*2+p)*8 + kk ----
    // Global W[o] is contiguous: g = ap*2048 + d*8 + kk  (ap in [0,8))
    const float* Wo = W + (size_t)o * (DIM * COLS);
    for (int i = threadIdx.x; i < DIM * COLS / 4; i += THREADS) {
        float4 v = reinterpret_cast<const float4*>(Wo)[i];
        int g  = i * 4;
        int ap = g >> 11;
        int d  = (g & 2047) >> 3;
        int kk = g & 7;                    // 0 or 4
        *reinterpret_cast<float4*>(&Ws[d * COLS + ap * 8 + kk]) = v;
    }
    if (threadIdx.x < COLS) bs[threadIdx.x] = bias[o * COLS + threadIdx.x];
    __syncthreads();

    // Thread tile: 4 rows x 16 cols (8 f32x2 pairs)
    const int tx = threadIdx.x & 3;        // col group: cols [tx*16, tx*16+16)
    const int ty = threadIdx.x >> 2;       // row group: rows [ty*4, ty*4+4)

    unsigned long long acc[4][8];
    #pragma unroll
    for (int p = 0; p < 8; p++) {
        unsigned long long bv =
            *reinterpret_cast<const unsigned long long*>(&bs[tx * 16 + p * 2]);
        #pragma unroll
        for (int i = 0; i < 4; i++) acc[i][p] = bv;
    }

    const int q   = threadIdx.x & 7;       // k-quad within chunk
    const int rl0 = threadIdx.x >> 3;      // loader row

    for (int kc = 0; kc < DIM; kc += KC) {
        // ---- Stage x chunk: xs[k][row] (transposed, padded) ----
        #pragma unroll
        for (int pass = 0; pass < 8; pass++) {
            int rl = rl0 + pass * 32;
            float4 v = *reinterpret_cast<const float4*>(
                x + (size_t)(row0 + rl) * 4096 + o * 256 + kc + q * 4);
            xs[(q * 4 + 0) * XS_STRIDE + rl] = v.x;
            xs[(q * 4 + 1) * XS_STRIDE + rl] = v.y;
            xs[(q * 4 + 2) * XS_STRIDE + rl] = v.z;
            xs[(q * 4 + 3) * XS_STRIDE + rl] = v.w;
        }
        __syncthreads();

        #pragma unroll 4
        for (int k = 0; k < KC; k++) {
            unsigned long long xp[4];
            #pragma unroll
            for (int i = 0; i < 4; i++)
                xp[i] = bcast2(xs[k * XS_STRIDE + ty * 4 + i]);

            // BUGFIX (R4): W row is the GLOBAL dim index kc+k, not the
            // within-chunk k. Previous rounds multiplied every chunk of x
            // against dims [0,32) of W -> rel_err 1.32.
            const float* wr = &Ws[(kc + k) * COLS + tx * 16];
            ulonglong2 wv[4];
            #pragma unroll
            for (int j = 0; j < 4; j++)
                wv[j] = *reinterpret_cast<const ulonglong2*>(wr + j * 4);

            #pragma unroll
            for (int i = 0; i < 4; i++) {
                #pragma unroll
                for (int j = 0; j < 4; j++) {
                    fma2(acc[i][2 * j + 0], xp[i], wv[j].x);
                    fma2(acc[i][2 * j + 1], xp[i], wv[j].y);
                }
            }
        }
        __syncthreads();
    }

    // ---- Epilogue: out[b*1024 + o*64 + c], pairs are contiguous cols ----
    #pragma unroll
    for (int i = 0; i < 4; i++) {
        int row = row0 + ty * 4 + i;
        unsigned long long* dst = reinterpret_cast<unsigned long long*>(
            out + (size_t)row * 1024 + o * 64 + tx * 16);
        #pragma unroll
        for (int p = 0; p < 8; p++) dst[p] = acc[i][p];
    }
}

extern "C" void kernel_launch(void* const* d_in, const int* in_sizes, int n_in,
                              void* d_out, int out_size) {
    const float* x    = (const float*)d_in[0];   // [B,16,256]
    const float* W    = (const float*)d_in[1];   // [16,4,2,256,8]
    const float* bias = (const float*)d_in[2];   // [16,4,2,8]
    float*       out  = (float*)d_out;           // [B,16,4,2,8]

    const int B = in_sizes[0] / (16 * 256);      // 16384
    const int smem_bytes = (DIM * COLS + KC * XS_STRIDE + COLS) * 4;  // ~98.7 KB

    cudaFuncSetAttribute(obj_decoder_kernel,
                         cudaFuncAttributeMaxDynamicSharedMemorySize, smem_bytes);

    dim3 grid(B / BT, 16);
    obj_decoder_kernel<<<grid, THREADS, smem_bytes>>>(x, W, bias, out);
}

// round 9
// speedup vs baseline: 1.0663x; 1.0663x over previous
#include <cuda_runtime.h>

// Problem constants (fixed by the reference):
//   B=16384, N_OBJ=16, N_ATTR=4, N_PARAM=2, DIM_IN=256, D_ATTR=8
//   out[b,o,a,p,k]  -> per object o: GEMM [B,256] x [256,64]
#define THREADS 256
#define BT      256            // batch rows per block
#define KC      16             // k-chunk staged in smem
#define DIM     256            // DIM_IN
#define COLS    64             // N_ATTR*N_PARAM*D_ATTR

__device__ __forceinline__ void fma2(unsigned long long& d,
                                     unsigned long long a,
                                     unsigned long long b) {
    // packed 2-wide fp32 FMA (FFMA2)
    asm("fma.rn.f32x2 %0, %1, %2, %0;" : "+l"(d) : "l"(a), "l"(b));
}

__device__ __forceinline__ unsigned long long bcast2(float v) {
    unsigned long long r;
    asm("mov.b64 %0, {%1, %1};" : "=l"(r) : "f"(v));
    return r;
}

__global__ __launch_bounds__(THREADS, 2)
void obj_decoder_kernel(const float* __restrict__ x,      // [B,16,256]
                        const float* __restrict__ W,      // [16,4,2,256,8]
                        const float* __restrict__ bias,   // [16,4,2,8]
                        float* __restrict__ out) {        // [B,16,4,2,8]
    extern __shared__ float sm[];
    float* Ws = sm;                 // [DIM][COLS] = 64 KB, Ws[d][c]
    float* xs = sm + DIM * COLS;    // [KC][256] floats, XOR-swizzled, 16 KB

    const int o    = blockIdx.y;
    const int row0 = blockIdx.x * BT;
    const int tid  = threadIdx.x;

    // ---- Load W[o] into smem as Ws[d][c], c = (a*2+p)*8 + kk ----
    // Global W[o] contiguous: g = ap*2048 + d*8 + kk  (ap in [0,8))
    const float* Wo = W + (size_t)o * (DIM * COLS);
    #pragma unroll
    for (int n = 0; n < (DIM * COLS / 4) / THREADS; n++) {
        int i = tid + n * THREADS;
        float4 v = reinterpret_cast<const float4*>(Wo)[i];
        int g  = i * 4;
        int ap = g >> 11;
        int d  = (g & 2047) >> 3;
        int kk = g & 7;             // 0 or 4
        *reinterpret_cast<float4*>(&Ws[d * COLS + ap * 8 + kk]) = v;
    }

    // ---- Compute mapping: col group per WARP (uniform W reads),
    //      4 consecutive rows per lane (one LDS.128 for x) ----
    const int warp = tid >> 5;
    const int lane = tid & 31;
    const int cg   = warp & 3;          // cols [cg*16, cg*16+16)
    const int rh   = warp >> 2;         // row half: +rh*128
    const int g    = rh * 32 + lane;    // row group (of 4), 0..63

    // acc[i][p]: row g*4+i, col pair cg*16 + 2p. Init from bias (broadcast LDG).
    unsigned long long acc[4][8];
    {
        const unsigned long long* bp =
            reinterpret_cast<const unsigned long long*>(bias + o * COLS + cg * 16);
        #pragma unroll
        for (int p = 0; p < 8; p++) {
            unsigned long long bv = bp[p];
            #pragma unroll
            for (int i = 0; i < 4; i++) acc[i][p] = bv;
        }
    }

    // ---- Staging mapping: q = k-quad (0..3), r0 = row (0..63), 4 passes ----
    const int q  = tid & 3;
    const int r0 = tid >> 2;
    const float* xbase = x + (size_t)row0 * 4096 + o * 256;

    // Prefetch chunk 0 into registers
    float4 v[4];
    #pragma unroll
    for (int p = 0; p < 4; p++)
        v[p] = *reinterpret_cast<const float4*>(
            xbase + (size_t)(r0 + p * 64) * 4096 + q * 4);

    const float4* xs4 = reinterpret_cast<const float4*>(xs);

    for (int kc = 0; kc < DIM; kc += KC) {
        // ---- Store prefetched chunk to xs, XOR-swizzled:
        //      (k,row) -> xs[k*256 + (row ^ ((k>>2)<<3))]
        //      bank = (lane>>2) | (((warp^lane)&3)<<3): conflict-free.
        {
            const int sw = q << 3;      // (k>>2)==q for k=q*4+i
            #pragma unroll
            for (int p = 0; p < 4; p++) {
                int row = (r0 + p * 64) ^ sw;
                xs[(q * 4 + 0) * 256 + row] = v[p].x;
                xs[(q * 4 + 1) * 256 + row] = v[p].y;
                xs[(q * 4 + 2) * 256 + row] = v[p].z;
                xs[(q * 4 + 3) * 256 + row] = v[p].w;
            }
        }
        __syncthreads();

        // Prefetch next chunk (latency hidden by the FFMA2 stream below)
        if (kc + KC < DIM) {
            #pragma unroll
            for (int p = 0; p < 4; p++)
                v[p] = *reinterpret_cast<const float4*>(
                    xbase + (size_t)(r0 + p * 64) * 4096 + (kc + KC) + q * 4);
        }

        #pragma unroll
        for (int k = 0; k < KC; k++) {
            // x: one LDS.128, group index swizzled by (k>>2)<<1 (=2q)
            float4 xv = xs4[k * 64 + (g ^ ((k >> 2) << 1))];
            unsigned long long xp[4] = {bcast2(xv.x), bcast2(xv.y),
                                        bcast2(xv.z), bcast2(xv.w)};

            // W: warp-uniform address -> 4 broadcast LDS.128 (1 wf each)
            const float* wr = &Ws[(kc + k) * COLS + cg * 16];
            ulonglong2 wv[4];
            #pragma unroll
            for (int j = 0; j < 4; j++)
                wv[j] = *reinterpret_cast<const ulonglong2*>(wr + j * 4);

            #pragma unroll
            for (int i = 0; i < 4; i++) {
                #pragma unroll
                for (int j = 0; j < 4; j++) {
                    fma2(acc[i][2 * j + 0], xp[i], wv[j].x);
                    fma2(acc[i][2 * j + 1], xp[i], wv[j].y);
                }
            }
        }
        __syncthreads();
    }

    // ---- Epilogue: rows g*4+i, cols cg*16.. as 4x 16B stores per row ----
    #pragma unroll
    for (int i = 0; i < 4; i++) {
        int row = row0 + g * 4 + i;
        float* dst = out + (size_t)row * 1024 + o * 64 + cg * 16;
        #pragma unroll
        for (int j = 0; j < 4; j++) {
            ulonglong2 t;
            t.x = acc[i][2 * j + 0];
            t.y = acc[i][2 * j + 1];
            *reinterpret_cast<ulonglong2*>(dst + j * 4) = t;
        }
    }
}

extern "C" void kernel_launch(void* const* d_in, const int* in_sizes, int n_in,
                              void* d_out, int out_size) {
    const float* x    = (const float*)d_in[0];   // [B,16,256]
    const float* W    = (const float*)d_in[1];   // [16,4,2,256,8]
    const float* bias = (const float*)d_in[2];   // [16,4,2,8]
    float*       out  = (float*)d_out;           // [B,16,4,2,8]

    const int B = in_sizes[0] / (16 * 256);      // 16384
    const int smem_bytes = (DIM * COLS + KC * 256) * 4;  // 80 KB

    cudaFuncSetAttribute(obj_decoder_kernel,
                         cudaFuncAttributeMaxDynamicSharedMemorySize, smem_bytes);

    dim3 grid(B / BT, 16);
    obj_decoder_kernel<<<grid, THREADS, smem_bytes>>>(x, W, bias, out);
}

// round 10
// speedup vs baseline: 3.2523x; 3.0501x over previous
#include <cuda_runtime.h>
#include <cuda_bf16.h>
#include <cstdint>

// Problem constants (fixed by the reference):
//   B=16384, N_OBJ=16, N_ATTR=4, N_PARAM=2, DIM_IN=256, D_ATTR=8
//   out[b,o,a,p,k] -> per object o: GEMM [B,256] x [256,64]
//
// Strategy: bf16 split-precision (x=xh+xl, W=wh+wl; P = xh*wh + xh*wl + xl*wh)
// on mma.sync.m16n8k16 with fp32 accumulation. Memory-bound target ~80us.
#define THREADS 256
#define BT      128            // batch rows per block
#define KC      32             // k-chunk of x staged in smem (bf16 hi/lo)
#define DIM     256
#define APAD    40             // A row stride in bf16 (KC+8) -> LDSM conflict-free
#define WPAD    264            // Wt row stride in bf16 (DIM+8) -> LDSM conflict-free

// smem layout (bytes)
#define SM_WH   0              // Wt_hi [64][WPAD] bf16 : 33792
#define SM_WL   33792          // Wt_lo                 : 33792
#define SM_AH   67584          // A_hi  [BT][APAD] bf16 : 10240
#define SM_AL   77824          // A_lo                  : 10240
#define SM_BS   88064          // bias [64] f32         : 256
#define SM_TOT  88320

__device__ __forceinline__ uint32_t cvt_bf2(float hi, float lo) {
    // d = { bf16(hi) , bf16(lo) }  (lo in low half)
    uint32_t r;
    asm("cvt.rn.bf16x2.f32 %0, %1, %2;" : "=r"(r) : "f"(hi), "f"(lo));
    return r;
}

__device__ __forceinline__ void ldsm4(uint32_t r[4], uint32_t addr) {
    asm volatile("ldmatrix.sync.aligned.m8n8.x4.shared.b16 {%0,%1,%2,%3}, [%4];"
                 : "=r"(r[0]), "=r"(r[1]), "=r"(r[2]), "=r"(r[3]) : "r"(addr));
}

__device__ __forceinline__ void mma16816(float c[4], const uint32_t a[4],
                                         const uint32_t b[2]) {
    asm volatile(
        "mma.sync.aligned.m16n8k16.row.col.f32.bf16.bf16.f32 "
        "{%0,%1,%2,%3}, {%4,%5,%6,%7}, {%8,%9}, {%0,%1,%2,%3};"
        : "+f"(c[0]), "+f"(c[1]), "+f"(c[2]), "+f"(c[3])
        : "r"(a[0]), "r"(a[1]), "r"(a[2]), "r"(a[3]), "r"(b[0]), "r"(b[1]));
}

// Split a float4 (4 consecutive k of x) into packed bf16 hi / lo pairs.
// lo = x - float(hi) is EXACT in fp32 (Dekker), so xh+xl = x to ~2^-18 rel.
__device__ __forceinline__ void split4(float4 v, uint2& hi, uint2& lo) {
    uint32_t h0 = cvt_bf2(v.y, v.x);
    uint32_t h1 = cvt_bf2(v.w, v.z);
    float f0 = __uint_as_float(h0 << 16);
    float f1 = __uint_as_float(h0 & 0xffff0000u);
    float f2 = __uint_as_float(h1 << 16);
    float f3 = __uint_as_float(h1 & 0xffff0000u);
    uint32_t l0 = cvt_bf2(v.y - f1, v.x - f0);
    uint32_t l1 = cvt_bf2(v.w - f3, v.z - f2);
    hi = make_uint2(h0, h1);
    lo = make_uint2(l0, l1);
}

__global__ __launch_bounds__(THREADS, 2)
void obj_decoder_mma(const float* __restrict__ x,      // [B,16,256]
                     const float* __restrict__ W,      // [16,4,2,256,8]
                     const float* __restrict__ bias,   // [16,4,2,8]
                     float* __restrict__ out) {        // [B,16,4,2,8]
    extern __shared__ char sm[];
    const int tid  = threadIdx.x;
    const int o    = blockIdx.y;
    const int row0 = blockIdx.x * BT;

    const uint32_t smb = (uint32_t)__cvta_generic_to_shared(sm);

    // ---- Start x chunk-0 prefetch first (longest latency) ----
    const int q  = tid & 7;            // k-quad: k = q*4
    const int r  = tid >> 3;           // 0..31 -> rows r + 32p
    const float* xb = x + (size_t)row0 * 4096 + o * 256;
    float4 v[4];
    #pragma unroll
    for (int p = 0; p < 4; p++)
        v[p] = *reinterpret_cast<const float4*>(
            xb + (size_t)(r + p * 32) * 4096 + q * 4);

    // ---- Convert W[o] -> Wt_hi/Wt_lo [col n][dim k] bf16, padded ----
    // W[o] contiguous: g = ap*2048 + d*8 + kk ; column c = ap*8 + kk
    {
        const float* Wo = W + (size_t)o * (DIM * 64);
        unsigned short* wh = (unsigned short*)(sm + SM_WH);
        unsigned short* wl = (unsigned short*)(sm + SM_WL);
        #pragma unroll
        for (int n = 0; n < 16; n++) {
            int i = tid + n * THREADS;                 // float4 idx, 4096 total
            float4 w4 = reinterpret_cast<const float4*>(Wo)[i];
            int g  = i * 4;
            int ap = g >> 11;
            int d  = (g >> 3) & 255;
            int c  = ap * 8 + (g & 7);
            float wv[4] = {w4.x, w4.y, w4.z, w4.w};
            #pragma unroll
            for (int j = 0; j < 4; j++) {
                unsigned short hu;
                asm("cvt.rn.bf16.f32 %0, %1;" : "=h"(hu) : "f"(wv[j]));
                float hf = __uint_as_float(((uint32_t)hu) << 16);
                float lf = wv[j] - hf;
                unsigned short lu;
                asm("cvt.rn.bf16.f32 %0, %1;" : "=h"(lu) : "f"(lf));
                wh[(c + j) * WPAD + d] = hu;
                wl[(c + j) * WPAD + d] = lu;
            }
        }
        if (tid < 64) ((float*)(sm + SM_BS))[tid] = bias[o * 64 + tid];
    }

    // ---- Warp tiling: 8 warps -> 4 row-groups x 2 col-groups ----
    const int warp = tid >> 5, lane = tid & 31;
    const int wx = warp & 1;                 // cols [wx*32, +32): 4 n8 tiles
    const int wy = warp >> 1;                // rows [wy*32, +32): 2 m16 tiles

    // ldmatrix lane address components
    const int a_row = lane & 15;             // + m0
    const int a_k8  = (lane >> 4);           // 0/1 -> +8 k
    const int b_n   = ((lane >> 4) << 3) + (lane & 7);   // + n0
    const int b_k8  = (lane >> 3) & 1;       // 0/1 -> +8 k

    const uint32_t ah_lane = smb + SM_AH + (a_row * APAD + a_k8 * 8) * 2;
    const uint32_t al_lane = smb + SM_AL + (a_row * APAD + a_k8 * 8) * 2;
    const uint32_t wh_lane = smb + SM_WH + (b_n * WPAD + b_k8 * 8) * 2;
    const uint32_t wl_lane = smb + SM_WL + (b_n * WPAD + b_k8 * 8) * 2;

    float acc[2][4][4];
    #pragma unroll
    for (int mt = 0; mt < 2; mt++)
        #pragma unroll
        for (int nt = 0; nt < 4; nt++)
            #pragma unroll
            for (int e = 0; e < 4; e++) acc[mt][nt][e] = 0.0f;

    // ---- Main loop over 8 k-chunks of 32 ----
    for (int kc = 0; kc < DIM / KC; kc++) {
        // store prefetched chunk as bf16 hi/lo (split during store)
        {
            uint32_t base = smb + (q * 8) * 1;  // byte offset of k within row
            #pragma unroll
            for (int p = 0; p < 4; p++) {
                uint2 hi, lo;
                split4(v[p], hi, lo);
                uint32_t rowoff = (uint32_t)(r + p * 32) * (APAD * 2) + q * 8;
                asm volatile("st.shared.v2.b32 [%0], {%1,%2};"
                             :: "r"(smb + SM_AH + rowoff), "r"(hi.x), "r"(hi.y));
                asm volatile("st.shared.v2.b32 [%0], {%1,%2};"
                             :: "r"(smb + SM_AL + rowoff), "r"(lo.x), "r"(lo.y));
            }
            (void)base;
        }
        __syncthreads();

        // prefetch next chunk
        if (kc + 1 < DIM / KC) {
            #pragma unroll
            for (int p = 0; p < 4; p++)
                v[p] = *reinterpret_cast<const float4*>(
                    xb + (size_t)(r + p * 32) * 4096 + (kc + 1) * KC + q * 4);
        }

        #pragma unroll
        for (int ks = 0; ks < 2; ks++) {
            const int kg = kc * KC + ks * 16;    // global k for W
            // B fragments: hi and lo, 4 n8-tiles via 2x ldmatrix.x4 each
            uint32_t bh[4][2], bl[4][2];
            #pragma unroll
            for (int pr = 0; pr < 2; pr++) {
                const uint32_t off = ((wx * 32 + pr * 16) * WPAD + kg) * 2;
                uint32_t t[4];
                ldsm4(t, wh_lane + off);
                bh[pr * 2][0] = t[0]; bh[pr * 2][1] = t[1];
                bh[pr * 2 + 1][0] = t[2]; bh[pr * 2 + 1][1] = t[3];
                ldsm4(t, wl_lane + off);
                bl[pr * 2][0] = t[0]; bl[pr * 2][1] = t[1];
                bl[pr * 2 + 1][0] = t[2]; bl[pr * 2 + 1][1] = t[3];
            }
            #pragma unroll
            for (int mt = 0; mt < 2; mt++) {
                const uint32_t aoff = ((wy * 32 + mt * 16) * APAD + ks * 16) * 2;
                uint32_t a[4];
                ldsm4(a, ah_lane + aoff);                 // xh
                #pragma unroll
                for (int nt = 0; nt < 4; nt++) mma16816(acc[mt][nt], a, bh[nt]);
                #pragma unroll
                for (int nt = 0; nt < 4; nt++) mma16816(acc[mt][nt], a, bl[nt]);
                ldsm4(a, al_lane + aoff);                 // xl
                #pragma unroll
                for (int nt = 0; nt < 4; nt++) mma16816(acc[mt][nt], a, bh[nt]);
            }
        }
        __syncthreads();
    }

    // ---- Epilogue: c0,c1 -> (row, col..col+1); c2,c3 -> (row+8, ...) ----
    const float* bs = (const float*)(sm + SM_BS);
    const int erow = wy * 32 + (lane >> 2);
    const int ecol = wx * 32 + (lane & 3) * 2;
    #pragma unroll
    for (int mt = 0; mt < 2; mt++) {
        #pragma unroll
        for (int nt = 0; nt < 4; nt++) {
            const int col = ecol + nt * 8;
            const float b0 = bs[col], b1 = bs[col + 1];
            const int rrow = row0 + erow + mt * 16;
            float2 s0 = make_float2(acc[mt][nt][0] + b0, acc[mt][nt][1] + b1);
            *reinterpret_cast<float2*>(out + (size_t)rrow * 1024 + o * 64 + col) = s0;
            float2 s1 = make_float2(acc[mt][nt][2] + b0, acc[mt][nt][3] + b1);
            *reinterpret_cast<float2*>(out + (size_t)(rrow + 8) * 1024 + o * 64 + col) = s1;
        }
    }
}

extern "C" void kernel_launch(void* const* d_in, const int* in_sizes, int n_in,
                              void* d_out, int out_size) {
    const float* x    = (const float*)d_in[0];   // [B,16,256]
    const float* W    = (const float*)d_in[1];   // [16,4,2,256,8]
    const float* bias = (const float*)d_in[2];   // [16,4,2,8]
    float*       out  = (float*)d_out;           // [B,16,4,2,8]

    const int B = in_sizes[0] / (16 * 256);      // 16384

    cudaFuncSetAttribute(obj_decoder_mma,
                         cudaFuncAttributeMaxDynamicSharedMemorySize, SM_TOT);

    dim3 grid(B / BT, 16);
    obj_decoder_mma<<<grid, THREADS, SM_TOT>>>(x, W, bias, out);
}